// round 16
// baseline (speedup 1.0000x reference)
#include <cuda_runtime.h>
#include <cuda_fp16.h>
#include <mma.h>
#include <math.h>
#include <stdint.h>

using namespace nvcuda;

#define T_SEQ 80
#define BATCH 128
#define EMB   100
#define KPAD  128
#define UNITS 2048
#define G3    6144
#define NCTA  128
#define THREADS 512

// ---------------- device scratch (allocation-free) ----------------
__device__ __half g_Bp0[(size_t)UNITS * G3];          // r0 packed [64 u][2048 k][96 col]
__device__ __half g_Bp1[(size_t)UNITS * G3];          // r1 packed [64 u][2048 k][96 col]
__device__ __half g_Bp2[(size_t)UNITS * G3];          // k1 packed [128 u][2048 k][48 col]
__device__ __half g_k0h[(size_t)KPAD * G3];
__device__ __half g_xh [(size_t)T_SEQ * BATCH * KPAD];
__device__ __half g_gi0h[(size_t)T_SEQ * BATCH * G3];
__device__ float  g_gh1[(size_t)BATCH * G3];
__device__ float  g_h0f[2][(size_t)BATCH * UNITS];
__device__ float  g_h1f[2][(size_t)BATCH * UNITS];
__device__ __half g_h0h[2][(size_t)BATCH * UNITS];
__device__ __half g_h1h[2][(size_t)BATCH * UNITS];
// dependency counters: [0]=c1 z0-K1 done (64), [1]=c2 z1-K1 done (64), [2]=c3 K2 done (128)
__device__ unsigned g_cnt[3][T_SEQ];

// ---------------- fused prep ----------------
__global__ void prep_all(const int* __restrict__ tokens, const float* __restrict__ emb,
                         const float* __restrict__ k0) {
    const int stride = gridDim.x * blockDim.x;
    const int t0 = blockIdx.x * blockDim.x + threadIdx.x;
    for (int i = t0; i < KPAD * G3; i += stride) {
        int k = i / G3;
        g_k0h[i] = (k < EMB) ? __float2half(k0[i]) : __half(0);
    }
    for (int i = t0; i < T_SEQ * BATCH * KPAD; i += stride) {
        int e  = i & (KPAD - 1);
        int tb = i >> 7;
        int t  = tb >> 7;
        int b  = tb & 127;
        float v = 0.f;
        if (e < EMB) {
            int tok = tokens[b * T_SEQ + t];
            v = emb[(size_t)tok * EMB + e];
        }
        g_xh[i] = __float2half(v);
    }
    for (int i = t0; i < BATCH * UNITS; i += stride) {
        g_h0f[0][i] = 0.f; g_h1f[0][i] = 0.f;
        g_h0h[0][i] = __half(0); g_h1h[0][i] = __half(0);
    }
    for (int i = t0; i < 3 * T_SEQ; i += stride) g_cnt[i / T_SEQ][i % T_SEQ] = 0u;
}

// gate-interleave pack (proven): out[u][k][g*BNU+c] = W[k][g*2048 + u*BNU + c]
template<int BNU>
__global__ void pack_gates(const float* __restrict__ W, int which) {
    __half* out = (BNU == 16) ? g_Bp2 : (which ? g_Bp1 : g_Bp0);
    int idx = blockIdx.x * blockDim.x + threadIdx.x;
    if (idx >= UNITS * G3) return;
    const int BNW = 3 * BNU;
    int u   = idx / (UNITS * BNW);
    int r   = idx % (UNITS * BNW);
    int k   = r / BNW;
    int col = r % BNW;
    int g   = col / BNU, c = col % BNU;
    out[idx] = __float2half(W[(size_t)k * G3 + g * UNITS + u * BNU + c]);
}

// ---------------- sync primitives ----------------
__device__ __forceinline__ void arrive_cnt(unsigned* c) {
    __threadfence();               // all threads: own stores visible at gpu scope
    __syncthreads();               // all threads' fences done
    if (threadIdx.x == 0) atomicAdd(c, 1u);
}
__device__ __forceinline__ void wait_cnt(const unsigned* c, unsigned target) {
    while (__ldcg(c) < target) { __nanosleep(64); }   // uniform addr: broadcast poll
    __threadfence();               // acquire: order subsequent reads after flag
}

// ---------------- shared GEMM machinery (proven smem layout) ----------------
__device__ __forceinline__ void cpa16(void* s, const void* g) {
    unsigned sa = (unsigned)__cvta_generic_to_shared(s);
    asm volatile("cp.async.cg.shared.global [%0], [%1], 16;" :: "r"(sa), "l"(g));
}

#define N_STAGE 4

template<int BN> struct SmemT {
    union {
        struct { __half As[N_STAGE][128][72]; __half Bs[N_STAGE][64][BN + 8]; } s;
        float Cs[128][BN];
    } u;
};

template<int MODE>
__device__ __forceinline__ const __half* wptr(int z) {
    return (MODE == 0) ? (z ? g_Bp1 : g_Bp0) : g_Bp2;
}

// prefetch the next GEMM's weight stages 0..2 as ONE commit group
template<int MODE>
__device__ __forceinline__ void prefetch_w(char* smraw, int u, int z) {
    constexpr int BN = (MODE == 2) ? 48 : 96;
    constexpr int BV = BN / 8;
    SmemT<BN>& sm = *reinterpret_cast<SmemT<BN>*>(smraw);
    const __half* B = wptr<MODE>(z);
    const int tid = threadIdx.x;
    #pragma unroll
    for (int s = 0; s < 3; s++) {
        for (int i = tid; i < 64 * BV; i += THREADS) {
            int row = i / BV, c8 = (i % BV) * 8;
            cpa16(&sm.u.s.Bs[s][row][c8],
                  B + ((size_t)u * UNITS + s * 64 + row) * BN + c8);
        }
    }
    asm volatile("cp.async.commit_group;");
}

// step GEMM: assumes B stages 0..2 already in flight (one pending group).
// MODE 0 (K1): BN=96; z=0: gh0+combine->h0', z=1: gh1 raw. 16 mma warps, 8x2.
// MODE 2 (K2): BN=48; gi1+combine->h1'. 12 mma warps, 4x3; epilogue waits c2[t].
template<int MODE>
__device__ __forceinline__ void step_gemm(char* smraw, int u, int z, int t, int p,
                                          const float* __restrict__ bias) {
    constexpr int BN  = (MODE == 2) ? 48 : 96;
    constexpr int BNU = BN / 3;
    constexpr int NK  = UNITS / 64;            // 32
    constexpr int FM  = (MODE == 0) ? 1 : 2;
    constexpr int FN  = (MODE == 0) ? 3 : 1;
    constexpr int BV  = BN / 8;

    const __half* A;
    const __half* Bw = wptr<MODE>(z);
    const __half* gi = g_gi0h + (size_t)t * BATCH * G3;
    const float*  hprev;
    float*  hn_f = nullptr;
    __half* hn_h = nullptr;

    if (MODE == 0) {
        A = z ? g_h1h[p] : g_h0h[p];
        hprev = g_h0f[p]; hn_f = g_h0f[p ^ 1]; hn_h = g_h0h[p ^ 1];
    } else {
        A = g_h0h[p ^ 1];
        hprev = g_h1f[p]; hn_f = g_h1f[p ^ 1]; hn_h = g_h1h[p ^ 1];
    }

    SmemT<BN>& sm = *reinterpret_cast<SmemT<BN>*>(smraw);
    const int tid  = threadIdx.x;
    const int warp = tid >> 5;

    auto loadA = [&](int st, int kb) {
        #pragma unroll
        for (int r = 0; r < 2; r++) {
            int i = tid + r * THREADS;
            int row = i >> 3, c8 = (i & 7) * 8;
            cpa16(&sm.u.s.As[st][row][c8], A + (size_t)row * UNITS + kb * 64 + c8);
        }
    };
    auto loadB = [&](int st, int kb) {
        for (int i = tid; i < 64 * BV; i += THREADS) {
            int row = i / BV, c8 = (i % BV) * 8;
            cpa16(&sm.u.s.Bs[st][row][c8],
                  Bw + ((size_t)u * UNITS + kb * 64 + row) * BN + c8);
        }
    };

    // A-prologue: B{0,1,2} already pending as 1 group
    loadA(0, 0); asm volatile("cp.async.commit_group;");
    loadA(1, 1); asm volatile("cp.async.commit_group;");
    loadA(2, 2); asm volatile("cp.async.commit_group;");

    int wm, wn; bool domma;
    if (MODE == 0) { wm = (warp >> 1) * 16; wn = (warp & 1) * 48; domma = true; }
    else           { wm = (warp / 3) * 32;  wn = (warp % 3) * 16; domma = (warp < 12); }

    wmma::fragment<wmma::accumulator, 16, 16, 16, float> acc[FM][FN];
    #pragma unroll
    for (int i = 0; i < FM; i++)
        #pragma unroll
        for (int j = 0; j < FN; j++)
            wmma::fill_fragment(acc[i][j], 0.f);

    for (int kb = 0; kb < NK; kb++) {
        const int cur = kb & (N_STAGE - 1);
        asm volatile("cp.async.wait_group 2;");
        __syncthreads();
        if (kb + 3 < NK) {
            loadA((kb + 3) & (N_STAGE - 1), kb + 3);
            loadB((kb + 3) & (N_STAGE - 1), kb + 3);
            asm volatile("cp.async.commit_group;");
        } else {
            asm volatile("cp.async.commit_group;");
        }

        if (domma) {
            #pragma unroll
            for (int kk = 0; kk < 64; kk += 16) {
                wmma::fragment<wmma::matrix_a, 16, 16, 16, __half, wmma::row_major> af[FM];
                wmma::fragment<wmma::matrix_b, 16, 16, 16, __half, wmma::row_major> bf[FN];
                #pragma unroll
                for (int i = 0; i < FM; i++)
                    wmma::load_matrix_sync(af[i], &sm.u.s.As[cur][wm + 16 * i][kk], 72);
                #pragma unroll
                for (int j = 0; j < FN; j++)
                    wmma::load_matrix_sync(bf[j], &sm.u.s.Bs[cur][kk][wn + 16 * j], BN + 8);
                #pragma unroll
                for (int i = 0; i < FM; i++)
                    #pragma unroll
                    for (int j = 0; j < FN; j++)
                        wmma::mma_sync(acc[i][j], af[i], bf[j], acc[i][j]);
            }
        }
    }

    asm volatile("cp.async.wait_group 0;");
    __syncthreads();

    if (domma) {
        #pragma unroll
        for (int i = 0; i < FM; i++)
            #pragma unroll
            for (int j = 0; j < FN; j++)
                wmma::store_matrix_sync(&sm.u.Cs[wm + 16 * i][wn + 16 * j],
                                        acc[i][j], BN, wmma::mem_row_major);
    }
    __syncthreads();

    if (MODE == 2) wait_cnt(&g_cnt[1][t], 64);   // g_gh1 complete (z1-K1 done)

    if ((MODE == 0 && z == 0) || MODE == 2) {
        for (int e = tid; e < 128 * BNU; e += THREADS) {
            int b = e / BNU, c = e % BNU;
            int j = u * BNU + c;
            float az = sm.u.Cs[b][c];
            float ar = sm.u.Cs[b][BNU + c];
            float ah = sm.u.Cs[b][2 * BNU + c];
            float giz, gir, gih, ghz, ghr, ghh;
            if (MODE == 0) {
                giz = __half2float(gi[(size_t)b * G3 + j]);
                gir = __half2float(gi[(size_t)b * G3 + UNITS + j]);
                gih = __half2float(gi[(size_t)b * G3 + 2 * UNITS + j]);
                ghz = az; ghr = ar; ghh = ah;
            } else {
                giz = az; gir = ar; gih = ah;
                // cross-CTA per-step data: L2-coherent loads (persistent kernel)
                ghz = __ldcg(&g_gh1[(size_t)b * G3 + j]);
                ghr = __ldcg(&g_gh1[(size_t)b * G3 + UNITS + j]);
                ghh = __ldcg(&g_gh1[(size_t)b * G3 + 2 * UNITS + j]);
            }
            float zg = 1.f / (1.f + __expf(-(giz + bias[j] + ghz + bias[G3 + j])));
            float rg = 1.f / (1.f + __expf(-(gir + bias[UNITS + j] + ghr + bias[G3 + UNITS + j])));
            float cd = tanhf(gih + bias[2 * UNITS + j] + rg * (ghh + bias[G3 + 2 * UNITS + j]));
            float hp = hprev[(size_t)b * UNITS + j];
            float hn = zg * hp + (1.f - zg) * cd;
            hn_f[(size_t)b * UNITS + j] = hn;
            hn_h[(size_t)b * UNITS + j] = __float2half(hn);
        }
    } else {    // MODE 0, z == 1: raw gh1 store, float4-vectorized
        for (int e = tid; e < 128 * 24; e += THREADS) {
            int b = e / 24, q = e % 24;
            int g = q >> 3, c4 = (q & 7) * 4;
            float4 v = *(const float4*)&sm.u.Cs[b][g * 32 + c4];
            *(float4*)&g_gh1[(size_t)b * G3 + g * UNITS + u * 32 + c4] = v;
        }
    }
}

// ---------------- persistent all-steps kernel (counter-synced) ----------------
__global__ __launch_bounds__(THREADS, 1)
void rnn_persist(const float* __restrict__ b0, const float* __restrict__ b1) {
    extern __shared__ char smraw[];
    const int cid = blockIdx.x;        // 0..127
    const int u1 = cid & 63;
    const int z1 = cid >> 6;
    prefetch_w<0>(smraw, u1, z1);
    for (int t = 0; t < T_SEQ; t++) {
        const int p = t & 1;
        if (t > 0) {
            if (z1 == 0) {                     // writes h0[p^1... needs K2(t-2) readers done
                wait_cnt(&g_cnt[0][t - 1], 64);    // A = h0h written by z0-K1(t-1)
                wait_cnt(&g_cnt[1][t - 1], 64);    // orders all K2(t-2) done (WAR)
            } else {
                wait_cnt(&g_cnt[2][t - 1], 128);   // A = h1h written by K2(t-1); gh1 WAR
            }
        }
        step_gemm<0>(smraw, u1, z1, t, p, b0);     // gh0+combine(h0') || gh1 raw
        arrive_cnt(&g_cnt[z1 ? 1 : 0][t]);
        prefetch_w<2>(smraw, cid, 0);
        wait_cnt(&g_cnt[0][t], 64);                // h0' complete
        step_gemm<2>(smraw, cid, 0, t, p, b1);     // gi1+combine(h1'); waits c2 inside
        arrive_cnt(&g_cnt[2][t]);
        if (t + 1 < T_SEQ) prefetch_w<0>(smraw, u1, z1);
    }
}

// ---------------- one-time gi0 = x @ k0 (proven, standalone 256-thread) ----------------
__global__ __launch_bounds__(256)
void gi0_kernel() {
    constexpr int BN = 96, NK = KPAD / 64;     // 2
    const int u = blockIdx.x;
    const __half* A = g_xh;
    const __half* B = g_k0h;
    extern __shared__ char smraw[];
    SmemT<96>& sm = *reinterpret_cast<SmemT<96>*>(smraw);
    const int tid = threadIdx.x;
    const size_t aRow0 = (size_t)blockIdx.y * 128;

    auto loadStage = [&](int st, int kb) {
        #pragma unroll
        for (int r = 0; r < 4; r++) {
            int i = tid + r * 256;
            int row = i >> 3, c8 = (i & 7) * 8;
            cpa16(&sm.u.s.As[st][row][c8], A + (aRow0 + row) * KPAD + kb * 64 + c8);
        }
        #pragma unroll
        for (int i = tid; i < 64 * 12; i += 256) {
            int row = i / 12, c8 = (i % 12) * 8;
            cpa16(&sm.u.s.Bs[st][row][c8], B + (size_t)(kb * 64 + row) * G3 + u * BN + c8);
        }
        asm volatile("cp.async.commit_group;");
    };

    const int warp = tid >> 5;
    const int wm = (warp / 2) * 32;
    const int wn = (warp % 2) * 48;

    wmma::fragment<wmma::accumulator, 16, 16, 16, float> acc[2][3];
    #pragma unroll
    for (int i = 0; i < 2; i++)
        #pragma unroll
        for (int j = 0; j < 3; j++)
            wmma::fill_fragment(acc[i][j], 0.f);

    #pragma unroll
    for (int s = 0; s < 3; s++) {
        if (s < NK) loadStage(s, s);
        else        asm volatile("cp.async.commit_group;");
    }
    for (int kb = 0; kb < NK; kb++) {
        const int cur = kb & 3;
        asm volatile("cp.async.wait_group 2;");
        __syncthreads();
        asm volatile("cp.async.commit_group;");
        #pragma unroll
        for (int kk = 0; kk < 64; kk += 16) {
            wmma::fragment<wmma::matrix_a, 16, 16, 16, __half, wmma::row_major> af[2];
            wmma::fragment<wmma::matrix_b, 16, 16, 16, __half, wmma::row_major> bf[3];
            #pragma unroll
            for (int i = 0; i < 2; i++)
                wmma::load_matrix_sync(af[i], &sm.u.s.As[cur][wm + 16 * i][kk], 72);
            #pragma unroll
            for (int j = 0; j < 3; j++)
                wmma::load_matrix_sync(bf[j], &sm.u.s.Bs[cur][kk][wn + 16 * j], 104);
            #pragma unroll
            for (int i = 0; i < 2; i++)
                #pragma unroll
                for (int j = 0; j < 3; j++)
                    wmma::mma_sync(acc[i][j], af[i], bf[j], acc[i][j]);
        }
    }
    asm volatile("cp.async.wait_group 0;");
    __syncthreads();
    #pragma unroll
    for (int i = 0; i < 2; i++)
        #pragma unroll
        for (int j = 0; j < 3; j++)
            wmma::store_matrix_sync(&sm.u.Cs[wm + 16 * i][wn + 16 * j],
                                    acc[i][j], 96, wmma::mem_row_major);
    __syncthreads();
    for (int e = tid; e < 128 * 96; e += 256) {
        int row = e / 96, col = e % 96;
        g_gi0h[(aRow0 + row) * G3 + u * 96 + col] = __float2half(sm.u.Cs[row][col]);
    }
}

// ---------------- head ----------------
__global__ void out_kernel(const float* __restrict__ wout, const float* __restrict__ bout,
                           float* __restrict__ out) {
    __shared__ float red[256];
    int b = blockIdx.x, tid = threadIdx.x;
    float s = 0.f;
    for (int j = tid; j < UNITS; j += 256)
        s += g_h1f[0][(size_t)b * UNITS + j] * wout[j];
    red[tid] = s; __syncthreads();
    for (int off = 128; off > 0; off >>= 1) {
        if (tid < off) red[tid] += red[tid + off];
        __syncthreads();
    }
    if (tid == 0) out[b] = 1.f / (1.f + expf(-(red[0] + bout[0])));
}

extern "C" void kernel_launch(void* const* d_in, const int* in_sizes, int n_in,
                              void* d_out, int out_size) {
    const int*   tokens = (const int*)  d_in[0];
    const float* emb    = (const float*)d_in[1];
    const float* k0     = (const float*)d_in[2];
    const float* r0     = (const float*)d_in[3];
    const float* b0     = (const float*)d_in[4];
    const float* k1     = (const float*)d_in[5];
    const float* r1     = (const float*)d_in[6];
    const float* b1     = (const float*)d_in[7];
    const float* wout   = (const float*)d_in[8];
    const float* bout   = (const float*)d_in[9];
    float* out = (float*)d_out;

    const int SMP = (int)sizeof(SmemT<96>);    // 126,976 B

    cudaFuncSetAttribute(rnn_persist, cudaFuncAttributeMaxDynamicSharedMemorySize, SMP);
    cudaFuncSetAttribute(gi0_kernel,  cudaFuncAttributeMaxDynamicSharedMemorySize, SMP);

    const int PK = (UNITS * G3 + 255) / 256;
    prep_all<<<592, 256>>>(tokens, emb, k0);
    pack_gates<32><<<PK, 256>>>(r0, 0);
    pack_gates<32><<<PK, 256>>>(r1, 1);
    pack_gates<16><<<PK, 256>>>(k1, 0);
    gi0_kernel<<<dim3(G3 / 96, T_SEQ, 1), 256, SMP>>>();

    rnn_persist<<<NCTA, THREADS, SMP>>>(b0, b1);

    out_kernel<<<BATCH, 256>>>(wout, bout, out);
}

// round 17
// speedup vs baseline: 1.1152x; 1.1152x over previous
#include <cuda_runtime.h>
#include <cuda_fp16.h>
#include <mma.h>
#include <math.h>
#include <stdint.h>

using namespace nvcuda;

#define T_SEQ 80
#define BATCH 128
#define EMB   100
#define KPAD  128
#define UNITS 2048
#define G3    6144
#define NCTA  128
#define THREADS 512

// ---------------- device scratch (allocation-free) ----------------
__device__ __half g_Bp0[(size_t)UNITS * G3];          // r0 packed [64 u][2048 k][96 col]
__device__ __half g_Bp1[(size_t)UNITS * G3];          // r1 packed [64 u][2048 k][96 col]
__device__ __half g_Bp2[(size_t)UNITS * G3];          // k1 packed [128 u][2048 k][48 col]
__device__ __half g_k0h[(size_t)KPAD * G3];
__device__ __half g_xh [(size_t)T_SEQ * BATCH * KPAD];
__device__ __half g_gi0h[(size_t)T_SEQ * BATCH * G3];
__device__ float  g_gh1[(size_t)BATCH * G3];
__device__ float  g_h0f[2][(size_t)BATCH * UNITS];
__device__ float  g_h1f[2][(size_t)BATCH * UNITS];
__device__ __half g_h0h[2][(size_t)BATCH * UNITS];
__device__ __half g_h1h[2][(size_t)BATCH * UNITS];
__device__ unsigned g_barc[2 * T_SEQ];

// ---------------- fused prep ----------------
__global__ void prep_all(const int* __restrict__ tokens, const float* __restrict__ emb,
                         const float* __restrict__ k0) {
    const int stride = gridDim.x * blockDim.x;
    const int t0 = blockIdx.x * blockDim.x + threadIdx.x;
    for (int i = t0; i < KPAD * G3; i += stride) {
        int k = i / G3;
        g_k0h[i] = (k < EMB) ? __float2half(k0[i]) : __half(0);
    }
    for (int i = t0; i < T_SEQ * BATCH * KPAD; i += stride) {
        int e  = i & (KPAD - 1);
        int tb = i >> 7;
        int t  = tb >> 7;
        int b  = tb & 127;
        float v = 0.f;
        if (e < EMB) {
            int tok = tokens[b * T_SEQ + t];
            v = emb[(size_t)tok * EMB + e];
        }
        g_xh[i] = __float2half(v);
    }
    for (int i = t0; i < BATCH * UNITS; i += stride) {
        g_h0f[0][i] = 0.f; g_h1f[0][i] = 0.f;
        g_h0h[0][i] = __half(0); g_h1h[0][i] = __half(0);
    }
    for (int i = t0; i < 2 * T_SEQ; i += stride) g_barc[i] = 0u;
}

// gate-interleave pack, 32-bit index math, one fused launch (gridDim.z = 3)
template<int BNU>
__device__ __forceinline__ void pack_body(const float* __restrict__ W,
                                          __half* __restrict__ out, unsigned idx) {
    const unsigned BNW = 3 * BNU;
    unsigned u   = idx / (UNITS * BNW);
    unsigned r   = idx % (UNITS * BNW);
    unsigned k   = r / BNW;
    unsigned col = r % BNW;
    unsigned g   = col / BNU, c = col % BNU;
    out[idx] = __float2half(W[k * (unsigned)G3 + g * (unsigned)UNITS + u * BNU + c]);
}
__global__ void pack3(const float* __restrict__ r0, const float* __restrict__ r1,
                      const float* __restrict__ k1) {
    unsigned idx = blockIdx.x * blockDim.x + threadIdx.x;
    if (idx >= (unsigned)UNITS * G3) return;     // all three targets have UNITS*G3 elems
    int z = blockIdx.z;
    if (z == 0)      pack_body<32>(r0, g_Bp0, idx);
    else if (z == 1) pack_body<32>(r1, g_Bp1, idx);
    else             pack_body<16>(k1, g_Bp2, idx);
}

// ---------------- shared GEMM machinery (proven smem layout) ----------------
__device__ __forceinline__ void cpa16(void* s, const void* g) {
    unsigned sa = (unsigned)__cvta_generic_to_shared(s);
    asm volatile("cp.async.cg.shared.global [%0], [%1], 16;" :: "r"(sa), "l"(g));
}

#define N_STAGE 4

template<int BN> struct SmemT {
    union {
        struct { __half As[N_STAGE][128][72]; __half Bs[N_STAGE][64][BN + 8]; } s;
        float Cs[128][BN];
    } u;
};

template<int MODE>
__device__ __forceinline__ const __half* wptr(int z) {
    return (MODE == 0) ? (z ? g_Bp1 : g_Bp0) : g_Bp2;
}

// prefetch the next GEMM's weight stages 0..2 as ONE commit group
template<int MODE>
__device__ __forceinline__ void prefetch_w(char* smraw, int u, int z) {
    constexpr int BN = (MODE == 2) ? 48 : 96;
    constexpr int BV = BN / 8;
    SmemT<BN>& sm = *reinterpret_cast<SmemT<BN>*>(smraw);
    const __half* B = wptr<MODE>(z);
    const int tid = threadIdx.x;
    #pragma unroll
    for (int s = 0; s < 3; s++) {
        for (int i = tid; i < 64 * BV; i += THREADS) {
            int row = i / BV, c8 = (i % BV) * 8;
            cpa16(&sm.u.s.Bs[s][row][c8],
                  B + ((size_t)u * UNITS + s * 64 + row) * BN + c8);
        }
    }
    asm volatile("cp.async.commit_group;");
}

// step GEMM: B stages 0..2 already in flight as one group.
// MODE 0 (K1): BN=96; z=0: gh0+combine->h0', z=1: gh1 raw. 16 mma warps, 8x2.
// MODE 2 (K2): BN=48; gi1+combine->h1'. 12 mma warps, 4x3.
template<int MODE>
__device__ __forceinline__ void step_gemm(char* smraw, int u, int z, int t, int p,
                                          const float* __restrict__ bias) {
    constexpr int BN  = (MODE == 2) ? 48 : 96;
    constexpr int BNU = BN / 3;
    constexpr int NK  = UNITS / 64;            // 32
    constexpr int FM  = (MODE == 0) ? 1 : 2;
    constexpr int FN  = (MODE == 0) ? 3 : 1;
    constexpr int BV  = BN / 8;

    const __half* A;
    const __half* Bw = wptr<MODE>(z);
    const __half* gi = g_gi0h + (size_t)t * BATCH * G3;
    const float*  hprev;
    float*  hn_f = nullptr;
    __half* hn_h = nullptr;

    if (MODE == 0) {
        A = z ? g_h1h[p] : g_h0h[p];
        hprev = g_h0f[p]; hn_f = g_h0f[p ^ 1]; hn_h = g_h0h[p ^ 1];
    } else {
        A = g_h0h[p ^ 1];
        hprev = g_h1f[p]; hn_f = g_h1f[p ^ 1]; hn_h = g_h1h[p ^ 1];
    }

    SmemT<BN>& sm = *reinterpret_cast<SmemT<BN>*>(smraw);
    const int tid  = threadIdx.x;
    const int warp = tid >> 5;

    auto loadA = [&](int st, int kb) {
        #pragma unroll
        for (int r = 0; r < 2; r++) {
            int i = tid + r * THREADS;
            int row = i >> 3, c8 = (i & 7) * 8;
            cpa16(&sm.u.s.As[st][row][c8], A + (size_t)row * UNITS + kb * 64 + c8);
        }
    };
    auto loadB = [&](int st, int kb) {
        for (int i = tid; i < 64 * BV; i += THREADS) {
            int row = i / BV, c8 = (i % BV) * 8;
            cpa16(&sm.u.s.Bs[st][row][c8],
                  Bw + ((size_t)u * UNITS + kb * 64 + row) * BN + c8);
        }
    };

    loadA(0, 0); asm volatile("cp.async.commit_group;");
    loadA(1, 1); asm volatile("cp.async.commit_group;");
    loadA(2, 2); asm volatile("cp.async.commit_group;");

    int wm, wn; bool domma;
    if (MODE == 0) { wm = (warp >> 1) * 16; wn = (warp & 1) * 48; domma = true; }
    else           { wm = (warp / 3) * 32;  wn = (warp % 3) * 16; domma = (warp < 12); }

    wmma::fragment<wmma::accumulator, 16, 16, 16, float> acc[FM][FN];
    #pragma unroll
    for (int i = 0; i < FM; i++)
        #pragma unroll
        for (int j = 0; j < FN; j++)
            wmma::fill_fragment(acc[i][j], 0.f);

    for (int kb = 0; kb < NK; kb++) {
        const int cur = kb & (N_STAGE - 1);
        asm volatile("cp.async.wait_group 2;");
        __syncthreads();
        if (kb + 3 < NK) {
            loadA((kb + 3) & (N_STAGE - 1), kb + 3);
            loadB((kb + 3) & (N_STAGE - 1), kb + 3);
            asm volatile("cp.async.commit_group;");
        } else {
            asm volatile("cp.async.commit_group;");
        }

        if (domma) {
            #pragma unroll
            for (int kk = 0; kk < 64; kk += 16) {
                wmma::fragment<wmma::matrix_a, 16, 16, 16, __half, wmma::row_major> af[FM];
                wmma::fragment<wmma::matrix_b, 16, 16, 16, __half, wmma::row_major> bf[FN];
                #pragma unroll
                for (int i = 0; i < FM; i++)
                    wmma::load_matrix_sync(af[i], &sm.u.s.As[cur][wm + 16 * i][kk], 72);
                #pragma unroll
                for (int j = 0; j < FN; j++)
                    wmma::load_matrix_sync(bf[j], &sm.u.s.Bs[cur][kk][wn + 16 * j], BN + 8);
                #pragma unroll
                for (int i = 0; i < FM; i++)
                    #pragma unroll
                    for (int j = 0; j < FN; j++)
                        wmma::mma_sync(acc[i][j], af[i], bf[j], acc[i][j]);
            }
        }
    }

    asm volatile("cp.async.wait_group 0;");
    __syncthreads();

    if (domma) {
        #pragma unroll
        for (int i = 0; i < FM; i++)
            #pragma unroll
            for (int j = 0; j < FN; j++)
                wmma::store_matrix_sync(&sm.u.Cs[wm + 16 * i][wn + 16 * j],
                                        acc[i][j], BN, wmma::mem_row_major);
    }
    __syncthreads();

    if ((MODE == 0 && z == 0) || MODE == 2) {
        // vectorized combine: 4 consecutive columns per lane-iteration
        constexpr int QPB = BNU / 4;                 // quads per batch row
        for (int e = tid; e < 128 * QPB; e += THREADS) {
            int b  = e / QPB;
            int c4 = (e % QPB) * 4;
            int j  = u * BNU + c4;
            float4 az4 = *(const float4*)&sm.u.Cs[b][c4];
            float4 ar4 = *(const float4*)&sm.u.Cs[b][BNU + c4];
            float4 ah4 = *(const float4*)&sm.u.Cs[b][2 * BNU + c4];
            float4 biz = *(const float4*)&bias[j];
            float4 bir = *(const float4*)&bias[UNITS + j];
            float4 bih = *(const float4*)&bias[2 * UNITS + j];
            float4 bhz = *(const float4*)&bias[G3 + j];
            float4 bhr = *(const float4*)&bias[G3 + UNITS + j];
            float4 bhh = *(const float4*)&bias[G3 + 2 * UNITS + j];
            float4 hp4 = *(const float4*)&hprev[(size_t)b * UNITS + j];

            float giz[4], gir[4], gih[4], ghz[4], ghr[4], ghh[4];
            if (MODE == 0) {
                uint2 vz = *(const uint2*)&gi[(size_t)b * G3 + j];
                uint2 vr = *(const uint2*)&gi[(size_t)b * G3 + UNITS + j];
                uint2 vh = *(const uint2*)&gi[(size_t)b * G3 + 2 * UNITS + j];
                const __half2* hz2 = (const __half2*)&vz;
                const __half2* hr2 = (const __half2*)&vr;
                const __half2* hh2 = (const __half2*)&vh;
                #pragma unroll
                for (int q = 0; q < 4; q++) {
                    __half2 p2;
                    p2 = hz2[q >> 1]; giz[q] = __half2float((q & 1) ? __high2half(p2) : __low2half(p2));
                    p2 = hr2[q >> 1]; gir[q] = __half2float((q & 1) ? __high2half(p2) : __low2half(p2));
                    p2 = hh2[q >> 1]; gih[q] = __half2float((q & 1) ? __high2half(p2) : __low2half(p2));
                }
                ghz[0]=az4.x; ghz[1]=az4.y; ghz[2]=az4.z; ghz[3]=az4.w;
                ghr[0]=ar4.x; ghr[1]=ar4.y; ghr[2]=ar4.z; ghr[3]=ar4.w;
                ghh[0]=ah4.x; ghh[1]=ah4.y; ghh[2]=ah4.z; ghh[3]=ah4.w;
            } else {
                float4 z4 = __ldcg((const float4*)&g_gh1[(size_t)b * G3 + j]);
                float4 r4 = __ldcg((const float4*)&g_gh1[(size_t)b * G3 + UNITS + j]);
                float4 h4 = __ldcg((const float4*)&g_gh1[(size_t)b * G3 + 2 * UNITS + j]);
                giz[0]=az4.x; giz[1]=az4.y; giz[2]=az4.z; giz[3]=az4.w;
                gir[0]=ar4.x; gir[1]=ar4.y; gir[2]=ar4.z; gir[3]=ar4.w;
                gih[0]=ah4.x; gih[1]=ah4.y; gih[2]=ah4.z; gih[3]=ah4.w;
                ghz[0]=z4.x; ghz[1]=z4.y; ghz[2]=z4.z; ghz[3]=z4.w;
                ghr[0]=r4.x; ghr[1]=r4.y; ghr[2]=r4.z; ghr[3]=r4.w;
                ghh[0]=h4.x; ghh[1]=h4.y; ghh[2]=h4.z; ghh[3]=h4.w;
            }
            const float* bizp = (const float*)&biz;
            const float* birp = (const float*)&bir;
            const float* bihp = (const float*)&bih;
            const float* bhzp = (const float*)&bhz;
            const float* bhrp = (const float*)&bhr;
            const float* bhhp = (const float*)&bhh;
            const float* hpp  = (const float*)&hp4;
            float hn[4];
            #pragma unroll
            for (int q = 0; q < 4; q++) {
                float zg = 1.f / (1.f + __expf(-(giz[q] + bizp[q] + ghz[q] + bhzp[q])));
                float rg = 1.f / (1.f + __expf(-(gir[q] + birp[q] + ghr[q] + bhrp[q])));
                float cd = tanhf(gih[q] + bihp[q] + rg * (ghh[q] + bhhp[q]));
                hn[q] = zg * hpp[q] + (1.f - zg) * cd;
            }
            *(float4*)&hn_f[(size_t)b * UNITS + j] = make_float4(hn[0], hn[1], hn[2], hn[3]);
            __half2 lo = __floats2half2_rn(hn[0], hn[1]);
            __half2 hi = __floats2half2_rn(hn[2], hn[3]);
            uint2 packed;
            packed.x = *(unsigned*)&lo;
            packed.y = *(unsigned*)&hi;
            *(uint2*)&hn_h[(size_t)b * UNITS + j] = packed;
        }
    } else {    // MODE 0, z == 1: raw gh1 store, float4-vectorized
        for (int e = tid; e < 128 * 24; e += THREADS) {
            int b = e / 24, q = e % 24;
            int g = q >> 3, c4 = (q & 7) * 4;
            float4 v = *(const float4*)&sm.u.Cs[b][g * 32 + c4];
            *(float4*)&g_gh1[(size_t)b * G3 + g * UNITS + u * 32 + c4] = v;
        }
    }
}

// ---------------- device-wide barrier (fresh counter per instance) ----------------
__device__ __forceinline__ void gridbar(int idx) {
    __syncthreads();
    if (threadIdx.x == 0) {
        __threadfence();
        atomicAdd(&g_barc[idx], 1u);
        while (((volatile unsigned*)g_barc)[idx] < NCTA) { __nanosleep(32); }
        __threadfence();
    }
    __syncthreads();
}

// ---------------- persistent all-steps kernel ----------------
__global__ __launch_bounds__(THREADS, 1)
void rnn_persist(const float* __restrict__ b0, const float* __restrict__ b1) {
    extern __shared__ char smraw[];
    const int cid = blockIdx.x;        // 0..127
    const int u1 = cid & 63;
    const int z1 = cid >> 6;
    prefetch_w<0>(smraw, u1, z1);
    for (int t = 0; t < T_SEQ; t++) {
        const int p = t & 1;
        step_gemm<0>(smraw, u1, z1, t, p, b0);    // gh0+combine(h0') || gh1 raw
        prefetch_w<2>(smraw, cid, 0);             // K2 weights ride the barrier wait
        gridbar(2 * t);
        step_gemm<2>(smraw, cid, 0, t, p, b1);    // gi1+combine(h1')
        if (t + 1 < T_SEQ) prefetch_w<0>(smraw, u1, z1);
        gridbar(2 * t + 1);
    }
}

// ---------------- one-time gi0 = x @ k0 (proven, standalone 256-thread) ----------------
__global__ __launch_bounds__(256)
void gi0_kernel() {
    constexpr int BN = 96, NK = KPAD / 64;     // 2
    const int u = blockIdx.x;
    const __half* A = g_xh;
    const __half* B = g_k0h;
    extern __shared__ char smraw[];
    SmemT<96>& sm = *reinterpret_cast<SmemT<96>*>(smraw);
    const int tid = threadIdx.x;
    const size_t aRow0 = (size_t)blockIdx.y * 128;

    auto loadStage = [&](int st, int kb) {
        #pragma unroll
        for (int r = 0; r < 4; r++) {
            int i = tid + r * 256;
            int row = i >> 3, c8 = (i & 7) * 8;
            cpa16(&sm.u.s.As[st][row][c8], A + (aRow0 + row) * KPAD + kb * 64 + c8);
        }
        #pragma unroll
        for (int i = tid; i < 64 * 12; i += 256) {
            int row = i / 12, c8 = (i % 12) * 8;
            cpa16(&sm.u.s.Bs[st][row][c8], B + (size_t)(kb * 64 + row) * G3 + u * BN + c8);
        }
        asm volatile("cp.async.commit_group;");
    };

    const int warp = tid >> 5;
    const int wm = (warp / 2) * 32;
    const int wn = (warp % 2) * 48;

    wmma::fragment<wmma::accumulator, 16, 16, 16, float> acc[2][3];
    #pragma unroll
    for (int i = 0; i < 2; i++)
        #pragma unroll
        for (int j = 0; j < 3; j++)
            wmma::fill_fragment(acc[i][j], 0.f);

    #pragma unroll
    for (int s = 0; s < 3; s++) {
        if (s < NK) loadStage(s, s);
        else        asm volatile("cp.async.commit_group;");
    }
    for (int kb = 0; kb < NK; kb++) {
        const int cur = kb & 3;
        asm volatile("cp.async.wait_group 2;");
        __syncthreads();
        asm volatile("cp.async.commit_group;");
        #pragma unroll
        for (int kk = 0; kk < 64; kk += 16) {
            wmma::fragment<wmma::matrix_a, 16, 16, 16, __half, wmma::row_major> af[2];
            wmma::fragment<wmma::matrix_b, 16, 16, 16, __half, wmma::row_major> bf[3];
            #pragma unroll
            for (int i = 0; i < 2; i++)
                wmma::load_matrix_sync(af[i], &sm.u.s.As[cur][wm + 16 * i][kk], 72);
            #pragma unroll
            for (int j = 0; j < 3; j++)
                wmma::load_matrix_sync(bf[j], &sm.u.s.Bs[cur][kk][wn + 16 * j], 104);
            #pragma unroll
            for (int i = 0; i < 2; i++)
                #pragma unroll
                for (int j = 0; j < 3; j++)
                    wmma::mma_sync(acc[i][j], af[i], bf[j], acc[i][j]);
        }
    }
    asm volatile("cp.async.wait_group 0;");
    __syncthreads();
    #pragma unroll
    for (int i = 0; i < 2; i++)
        #pragma unroll
        for (int j = 0; j < 3; j++)
            wmma::store_matrix_sync(&sm.u.Cs[wm + 16 * i][wn + 16 * j],
                                    acc[i][j], 96, wmma::mem_row_major);
    __syncthreads();
    for (int e = tid; e < 128 * 96; e += 256) {
        int row = e / 96, col = e % 96;
        g_gi0h[(aRow0 + row) * G3 + u * 96 + col] = __float2half(sm.u.Cs[row][col]);
    }
}

// ---------------- head ----------------
__global__ void out_kernel(const float* __restrict__ wout, const float* __restrict__ bout,
                           float* __restrict__ out) {
    __shared__ float red[256];
    int b = blockIdx.x, tid = threadIdx.x;
    float s = 0.f;
    for (int j = tid; j < UNITS; j += 256)
        s += g_h1f[0][(size_t)b * UNITS + j] * wout[j];
    red[tid] = s; __syncthreads();
    for (int off = 128; off > 0; off >>= 1) {
        if (tid < off) red[tid] += red[tid + off];
        __syncthreads();
    }
    if (tid == 0) out[b] = 1.f / (1.f + expf(-(red[0] + bout[0])));
}

extern "C" void kernel_launch(void* const* d_in, const int* in_sizes, int n_in,
                              void* d_out, int out_size) {
    const int*   tokens = (const int*)  d_in[0];
    const float* emb    = (const float*)d_in[1];
    const float* k0     = (const float*)d_in[2];
    const float* r0     = (const float*)d_in[3];
    const float* b0     = (const float*)d_in[4];
    const float* k1     = (const float*)d_in[5];
    const float* r1     = (const float*)d_in[6];
    const float* b1     = (const float*)d_in[7];
    const float* wout   = (const float*)d_in[8];
    const float* bout   = (const float*)d_in[9];
    float* out = (float*)d_out;

    const int SMP = (int)sizeof(SmemT<96>);    // 126,976 B

    cudaFuncSetAttribute(rnn_persist, cudaFuncAttributeMaxDynamicSharedMemorySize, SMP);
    cudaFuncSetAttribute(gi0_kernel,  cudaFuncAttributeMaxDynamicSharedMemorySize, SMP);

    prep_all<<<592, 256>>>(tokens, emb, k0);
    pack3<<<dim3((UNITS * G3 + 255) / 256, 1, 3), 256>>>(r0, r1, k1);
    gi0_kernel<<<dim3(G3 / 96, T_SEQ, 1), 256, SMP>>>();

    rnn_persist<<<NCTA, THREADS, SMP>>>(b0, b1);

    out_kernel<<<BATCH, 256>>>(wout, bout, out);
}